// round 10
// baseline (speedup 1.0000x reference)
#include <cuda_runtime.h>
#include <cstdint>

// Problem constants
#define BATCH 8
#define CIN   256
#define COUT  256
#define H     64
#define W     64
#define S     4096
#define K2    9
#define R     2304        // CIN*K2

// Scratch
__device__ float g_xt[(size_t)BATCH * S * CIN];     // x NHWC (raw fp32)
__device__ float g_colT[(size_t)BATCH * S * R];     // colT[b][s][k2*256+c], tf32-rounded
__device__ float g_wtp[(size_t)(R / 8) * COUT * 8]; // W permuted: [r/8][o][octet-interleaved]

__device__ __forceinline__ unsigned f2tf(float f) {
    unsigned r;
    asm("cvt.rna.tf32.f32 %0, %1;" : "=r"(r) : "f"(f));
    return r;
}

// ---------------------------------------------------------------------------
// Kernel 0: weight prepack into fragment-friendly permuted layout.
//   g_wtp[r>>3][o][slot] = tf32(w[o][c][k2]),  r = k2*256 + c,
//   slot = ((r&3)<<1) | ((r&7)>>2)
// ---------------------------------------------------------------------------
__global__ void __launch_bounds__(512) cvtw_k(const float* __restrict__ w) {
    const int j    = blockIdx.x * 512 + threadIdx.x;
    const int oct  = j >> 11;
    const int rem  = j & 2047;
    const int o    = rem >> 3;
    const int slot = rem & 7;
    const int r7   = (slot >> 1) + ((slot & 1) << 2);
    const int r    = oct * 8 + r7;
    const int k2   = r >> 8;
    const int c    = r & 255;
    g_wtp[j] = __uint_as_float(f2tf(w[o * R + c * 9 + k2]));
}

// ---------------------------------------------------------------------------
// Kernel 1: transpose x[b][c][s] -> g_xt[b][s][c]
// ---------------------------------------------------------------------------
__global__ void __launch_bounds__(256) trans_k(const float* __restrict__ x) {
    __shared__ float t[32][33];
    const int b  = blockIdx.z;
    const int s0 = blockIdx.x * 32;
    const int c0 = blockIdx.y * 32;
    const int tx = threadIdx.x, ty = threadIdx.y;
    const float* xb = x + ((size_t)b << 20);
#pragma unroll
    for (int i = ty; i < 32; i += 8)
        t[i][tx] = xb[(size_t)(c0 + i) * S + s0 + tx];
    __syncthreads();
    float* xtb = g_xt + ((size_t)b << 20);
#pragma unroll
    for (int i = ty; i < 32; i += 8)
        xtb[(size_t)(s0 + i) * CIN + c0 + tx] = t[tx][i];
}

// ---------------------------------------------------------------------------
// Kernel 2: im2colT — coalesced gather; one warp per output position s.
// ---------------------------------------------------------------------------
__global__ void __launch_bounds__(256) im2colT_k(const float* __restrict__ off) {
    const int warp = threadIdx.x >> 5;
    const int lane = threadIdx.x & 31;
    const int s = blockIdx.x * 8 + warp;
    const int b = blockIdx.y;
    const int ho = s >> 6, wo = s & 63;

    const float* Xb = g_xt + ((size_t)b << 20);
    float* op = g_colT + ((size_t)b * S + s) * R;

#pragma unroll
    for (int k2 = 0; k2 < K2; k2++) {
        const float dy = off[((size_t)b * 18 + 2 * k2)     * S + s];
        const float dx = off[((size_t)b * 18 + 2 * k2 + 1) * S + s];
        const float py = (float)(ho - 1 + k2 / 3) + dy;
        const float px = (float)(wo - 1 + k2 % 3) + dx;
        const float yf = floorf(py), xf = floorf(px);
        const int y0 = (int)yf, x0 = (int)xf;
        const float ly = py - yf, lx = px - xf;
        const float hy = 1.0f - ly, hx = 1.0f - lx;
        const bool vy0 = (y0 >= 0)  && (y0 < H);
        const bool vy1 = (y0 >= -1) && (y0 < H - 1);
        const bool vx0 = (x0 >= 0)  && (x0 < W);
        const bool vx1 = (x0 >= -1) && (x0 < W - 1);
        const float w00 = hy * hx * (float)(vy0 && vx0);
        const float w01 = hy * lx * (float)(vy0 && vx1);
        const float w10 = ly * hx * (float)(vy1 && vx0);
        const float w11 = ly * lx * (float)(vy1 && vx1);
        const int cy0 = min(max(y0, 0), H - 1);
        const int cy1 = min(max(y0 + 1, 0), H - 1);
        const int cx0 = min(max(x0, 0), W - 1);
        const int cx1 = min(max(x0 + 1, 0), W - 1);
        const float* p00 = Xb + (((size_t)(cy0 << 6) + cx0) << 8);
        const float* p01 = Xb + (((size_t)(cy0 << 6) + cx1) << 8);
        const float* p10 = Xb + (((size_t)(cy1 << 6) + cx0) << 8);
        const float* p11 = Xb + (((size_t)(cy1 << 6) + cx1) << 8);
        unsigned* od = (unsigned*)(op + (k2 << 8));

#pragma unroll
        for (int half = 0; half < 2; half++) {
            const int c = half * 128 + lane * 4;
            float4 a  = *(const float4*)(p00 + c);
            float4 bb = *(const float4*)(p01 + c);
            float4 cc = *(const float4*)(p10 + c);
            float4 dd = *(const float4*)(p11 + c);
            uint4 v;
            v.x = f2tf(w00 * a.x + w01 * bb.x + w10 * cc.x + w11 * dd.x);
            v.y = f2tf(w00 * a.y + w01 * bb.y + w10 * cc.y + w11 * dd.y);
            v.z = f2tf(w00 * a.z + w01 * bb.z + w10 * cc.z + w11 * dd.z);
            v.w = f2tf(w00 * a.w + w01 * bb.w + w10 * cc.w + w11 * dd.w);
            *(uint4*)(od + c) = v;
        }
    }
}

// ---------------------------------------------------------------------------
// Kernel 3: GEMM  C[b][s][o] = sum_r colT[b][s][r] * W[o][r]   (tf32 mma.sync)
//   CTA tile: 128 s x 128 o, 8 warps (2 x 4), warp tile 64x32, kTile 32,
//   3-stage cp.async, 2 CTAs/SM (16 warps/SM).
// ---------------------------------------------------------------------------
#define KTILE 32
#define NKT   72
#define A_LD  36                       // 32 + 4 pad
#define A_STW (128 * A_LD)             // 4608 words
#define B_STW (4 * 128 * 8)            // 4096 words
#define STW   (A_STW + B_STW)          // 8704 words
#define STAGES 3
#define SMEM_BYTES (STAGES * STW * 4)  // 104,448 B

#define CP_ASYNC16(dst, src) \
    asm volatile("cp.async.cg.shared.global [%0], [%1], 16;\n" :: "r"(dst), "l"(src))
#define CP_COMMIT() asm volatile("cp.async.commit_group;\n")
#define CP_WAIT2()  asm volatile("cp.async.wait_group 2;\n")

__device__ __forceinline__ void mma8(float* c, const unsigned* a, const unsigned* b) {
    asm volatile(
        "mma.sync.aligned.m16n8k8.row.col.f32.tf32.tf32.f32 "
        "{%0,%1,%2,%3}, {%4,%5,%6,%7}, {%8,%9}, {%0,%1,%2,%3};\n"
        : "+f"(c[0]), "+f"(c[1]), "+f"(c[2]), "+f"(c[3])
        : "r"(a[0]), "r"(a[1]), "r"(a[2]), "r"(a[3]), "r"(b[0]), "r"(b[1]));
}

__global__ void __launch_bounds__(256, 2) gemm_k(float* __restrict__ out) {
    extern __shared__ unsigned sm[];
    const unsigned smem_base = (unsigned)__cvta_generic_to_shared(sm);

    const int b     = blockIdx.z;
    const int mBase = blockIdx.x * 128;     // s
    const int nBase = blockIdx.y * 128;     // o

    const int tid  = threadIdx.x;
    const int warp = tid >> 5;
    const int lane = tid & 31;
    const int wm   = (warp >> 2) * 64;      // warp s offset (0/64)
    const int wn   = (warp & 3) * 32;       // warp o offset (0/32/64/96)
    const int g    = lane >> 2;
    const int tig  = lane & 3;

    const float* gA = g_colT + ((size_t)b * S + mBase) * R;

    float acc[4][4][4];
#pragma unroll
    for (int i = 0; i < 4; i++)
#pragma unroll
        for (int j = 0; j < 4; j++)
#pragma unroll
            for (int k = 0; k < 4; k++) acc[i][j][k] = 0.0f;

    // ---- stage fill: A 128s x 32k (padded), B 4oct x 128o x 8 (permuted) ----
    auto fill = [&](int st, int kt) {
        const int kb = kt * KTILE;
        const unsigned sa = smem_base + st * (STW * 4);
        const unsigned sb = sa + A_STW * 4;
#pragma unroll
        for (int i = 0; i < 4; i++) {        // A: 1024 x 16B granules
            const int gdx = i * 256 + tid;
            const int r = gdx >> 3, c4 = gdx & 7;
            CP_ASYNC16(sa + ((r * A_LD + c4 * 4) << 2),
                       gA + (size_t)r * R + kb + c4 * 4);
        }
        const float* gBk = g_wtp + ((size_t)(kb >> 3) * COUT + nBase) * 8;
#pragma unroll
        for (int i = 0; i < 4; i++) {        // B: 1024 x 16B granules
            const int gdx = i * 256 + tid;
            const int oct = gdx >> 8;
            const int rem = gdx & 255;
            const int ol  = rem >> 1;
            const int hf  = rem & 1;
            CP_ASYNC16(sb + (((oct * 128 + ol) * 8 + hf * 4) << 2),
                       gBk + ((size_t)oct * COUT + ol) * 8 + hf * 4);
        }
    };

    fill(0, 0); CP_COMMIT();
    fill(1, 1); CP_COMMIT();

    for (int kt = 0; kt < NKT; kt++) {
        __syncthreads();
        const int pf = kt + 2;
        if (pf < NKT) {
            int pst = kt + 2; pst -= (pst / STAGES) * STAGES;
            fill(pst, pf);
        }
        CP_COMMIT();
        CP_WAIT2();
        __syncthreads();

        int cs = kt - (kt / STAGES) * STAGES;
        const unsigned* A  = sm + cs * STW;
        const unsigned* Bm = A + A_STW;

#pragma unroll
        for (int ks = 0; ks < 4; ks++) {
            const int kk = ks * 8 + tig;
            unsigned af[4][4], bf[4][2];
#pragma unroll
            for (int mt = 0; mt < 4; mt++) {
                const int base = (wm + mt * 16 + g) * A_LD + kk;
                af[mt][0] = A[base];
                af[mt][1] = A[base + 8 * A_LD];
                af[mt][2] = A[base + 4];
                af[mt][3] = A[base + 8 * A_LD + 4];
            }
#pragma unroll
            for (int nt = 0; nt < 4; nt++) {
                const int nc = wn + nt * 8 + g;
                uint2 t = *(const uint2*)(Bm + ((ks * 128 + nc) << 3) + (tig << 1));
                bf[nt][0] = t.x;
                bf[nt][1] = t.y;
            }
#pragma unroll
            for (int mt = 0; mt < 4; mt++)
#pragma unroll
                for (int nt = 0; nt < 4; nt++)
                    mma8(acc[mt][nt], af[mt], bf[nt]);
        }
    }

    // ---- epilogue: transpose C[s][o] tile -> out[b][o][s] via smem ----
    __syncthreads();
    float* stg = (float*)sm;                  // [128 o][132]
#pragma unroll
    for (int mt = 0; mt < 4; mt++) {
#pragma unroll
        for (int nt = 0; nt < 4; nt++) {
            const int ol = wn + nt * 8 + 2 * tig;
            const int sl = wm + mt * 16 + g;
            stg[ol * 132 + sl]             = acc[mt][nt][0];
            stg[(ol + 1) * 132 + sl]       = acc[mt][nt][1];
            stg[ol * 132 + sl + 8]         = acc[mt][nt][2];
            stg[(ol + 1) * 132 + sl + 8]   = acc[mt][nt][3];
        }
    }
    __syncthreads();

    float* ob = out + ((size_t)b * COUT + nBase) * S + mBase;
#pragma unroll
    for (int i = 0; i < 16; i++) {
        const int e  = i * 256 + tid;
        const int o  = e >> 5;
        const int l4 = e & 31;
        *(float4*)(ob + (size_t)o * S + 4 * l4) = *(float4*)&stg[o * 132 + 4 * l4];
    }
}

// ---------------------------------------------------------------------------
extern "C" void kernel_launch(void* const* d_in, const int* in_sizes, int n_in,
                              void* d_out, int out_size) {
    const float* x   = (const float*)d_in[0];
    const float* off = (const float*)d_in[1];
    const float* wt  = (const float*)d_in[2];
    float* out       = (float*)d_out;

    cvtw_k<<<(COUT * R) / 512, 512>>>(wt);
    trans_k<<<dim3(S / 32, CIN / 32, BATCH), dim3(32, 8)>>>(x);
    im2colT_k<<<dim3(S / 8, BATCH), 256>>>(off);

    cudaFuncSetAttribute(gemm_k, cudaFuncAttributeMaxDynamicSharedMemorySize,
                         SMEM_BYTES);
    gemm_k<<<dim3(S / 128, COUT / 128, BATCH), 256, SMEM_BYTES>>>(out);
}

// round 13
// speedup vs baseline: 1.0822x; 1.0822x over previous
#include <cuda_runtime.h>
#include <cstdint>

// Problem constants
#define BATCH 8
#define CIN   256
#define COUT  256
#define H     64
#define W     64
#define S     4096
#define K2    9
#define R     2304        // CIN*K2

// Scratch
__device__ float g_xt[(size_t)BATCH * S * CIN];     // x NHWC (raw fp32)
__device__ float g_colT[(size_t)BATCH * S * R];     // colT[b][s][.], octet-PERMUTED tf32
__device__ float g_wtp[(size_t)(R / 8) * COUT * 8]; // W permuted: [r/8][o][octet-interleaved]

__device__ __forceinline__ unsigned f2tf(float f) {
    unsigned r;
    asm("cvt.rna.tf32.f32 %0, %1;" : "=r"(r) : "f"(f));
    return r;
}

// ---------------------------------------------------------------------------
// Kernel 0: weight prepack into fragment-friendly permuted layout.
//   g_wtp[r>>3][o][slot] = tf32(w[o][c][k2]),  r = k2*256 + c,
//   slot = ((r&3)<<1) | ((r&7)>>2)
// ---------------------------------------------------------------------------
__global__ void __launch_bounds__(512) cvtw_k(const float* __restrict__ w) {
    const int j    = blockIdx.x * 512 + threadIdx.x;
    const int oct  = j >> 11;
    const int rem  = j & 2047;
    const int o    = rem >> 3;
    const int slot = rem & 7;
    const int r7   = (slot >> 1) + ((slot & 1) << 2);
    const int r    = oct * 8 + r7;
    const int k2   = r >> 8;
    const int c    = r & 255;
    g_wtp[j] = __uint_as_float(f2tf(w[o * R + c * 9 + k2]));
}

// ---------------------------------------------------------------------------
// Kernel 1: transpose x[b][c][s] -> g_xt[b][s][c]
// ---------------------------------------------------------------------------
__global__ void __launch_bounds__(256) trans_k(const float* __restrict__ x) {
    __shared__ float t[32][33];
    const int b  = blockIdx.z;
    const int s0 = blockIdx.x * 32;
    const int c0 = blockIdx.y * 32;
    const int tx = threadIdx.x, ty = threadIdx.y;
    const float* xb = x + ((size_t)b << 20);
#pragma unroll
    for (int i = ty; i < 32; i += 8)
        t[i][tx] = xb[(size_t)(c0 + i) * S + s0 + tx];
    __syncthreads();
    float* xtb = g_xt + ((size_t)b << 20);
#pragma unroll
    for (int i = ty; i < 32; i += 8)
        xtb[(size_t)(s0 + i) * CIN + c0 + tx] = t[tx][i];
}

// ---------------------------------------------------------------------------
// Kernel 2: im2colT — coalesced gather, one warp per s; output stored with the
// SAME octet permutation as g_wtp, via a 4-shfl in-register swizzle.
//   physical word (c&~7)+slot holds logical channel c;  slot = ((c&3)<<1)|((c&7)>>2)
// Lane addresses are unchanged (uint4 at c = half*128 + lane*4); only data swizzles:
//   even lane stores {t.x, partner.x, t.y, partner.y}
//   odd  lane stores {partner.z, t.z, partner.w, t.w}
// ---------------------------------------------------------------------------
__global__ void __launch_bounds__(256) im2colT_k(const float* __restrict__ off) {
    const int warp = threadIdx.x >> 5;
    const int lane = threadIdx.x & 31;
    const int s = blockIdx.x * 8 + warp;
    const int b = blockIdx.y;
    const int ho = s >> 6, wo = s & 63;

    const float* Xb = g_xt + ((size_t)b << 20);
    float* op = g_colT + ((size_t)b * S + s) * R;

#pragma unroll
    for (int k2 = 0; k2 < K2; k2++) {
        const float dy = off[((size_t)b * 18 + 2 * k2)     * S + s];
        const float dx = off[((size_t)b * 18 + 2 * k2 + 1) * S + s];
        const float py = (float)(ho - 1 + k2 / 3) + dy;
        const float px = (float)(wo - 1 + k2 % 3) + dx;
        const float yf = floorf(py), xf = floorf(px);
        const int y0 = (int)yf, x0 = (int)xf;
        const float ly = py - yf, lx = px - xf;
        const float hy = 1.0f - ly, hx = 1.0f - lx;
        const bool vy0 = (y0 >= 0)  && (y0 < H);
        const bool vy1 = (y0 >= -1) && (y0 < H - 1);
        const bool vx0 = (x0 >= 0)  && (x0 < W);
        const bool vx1 = (x0 >= -1) && (x0 < W - 1);
        const float w00 = hy * hx * (float)(vy0 && vx0);
        const float w01 = hy * lx * (float)(vy0 && vx1);
        const float w10 = ly * hx * (float)(vy1 && vx0);
        const float w11 = ly * lx * (float)(vy1 && vx1);
        const int cy0 = min(max(y0, 0), H - 1);
        const int cy1 = min(max(y0 + 1, 0), H - 1);
        const int cx0 = min(max(x0, 0), W - 1);
        const int cx1 = min(max(x0 + 1, 0), W - 1);
        const float* p00 = Xb + (((size_t)(cy0 << 6) + cx0) << 8);
        const float* p01 = Xb + (((size_t)(cy0 << 6) + cx1) << 8);
        const float* p10 = Xb + (((size_t)(cy1 << 6) + cx0) << 8);
        const float* p11 = Xb + (((size_t)(cy1 << 6) + cx1) << 8);
        unsigned* od = (unsigned*)(op + (k2 << 8));

#pragma unroll
        for (int half = 0; half < 2; half++) {
            const int c = half * 128 + lane * 4;
            float4 a  = *(const float4*)(p00 + c);
            float4 bb = *(const float4*)(p01 + c);
            float4 cc = *(const float4*)(p10 + c);
            float4 dd = *(const float4*)(p11 + c);
            uint4 t;
            t.x = f2tf(w00 * a.x + w01 * bb.x + w10 * cc.x + w11 * dd.x);
            t.y = f2tf(w00 * a.y + w01 * bb.y + w10 * cc.y + w11 * dd.y);
            t.z = f2tf(w00 * a.z + w01 * bb.z + w10 * cc.z + w11 * dd.z);
            t.w = f2tf(w00 * a.w + w01 * bb.w + w10 * cc.w + w11 * dd.w);
            const unsigned sx = __shfl_xor_sync(0xffffffffu, t.x, 1);
            const unsigned sy = __shfl_xor_sync(0xffffffffu, t.y, 1);
            const unsigned sz = __shfl_xor_sync(0xffffffffu, t.z, 1);
            const unsigned sw = __shfl_xor_sync(0xffffffffu, t.w, 1);
            uint4 o;
            if ((lane & 1) == 0) o = make_uint4(t.x, sx, t.y, sy);
            else                 o = make_uint4(sz, t.z, sw, t.w);
            *(uint4*)(od + c) = o;
        }
    }
}

// ---------------------------------------------------------------------------
// Kernel 3: GEMM  C[b][s][o] = sum_r colT[b][s][r] * W[o][r]   (tf32 mma.sync)
//   R9 config: CTA 128s x 128o, 4 warps, warp tile 64x64, kTile 32,
//   3-stage cp.async, 2 CTAs/SM. BOTH operands octet-permuted ->
//   all fragment loads are LDS.64 (A: 8/ks, B: 8/ks).
// ---------------------------------------------------------------------------
#define KTILE 32
#define NKT   72
#define A_LD  40                       // 32 + 8 pad: conflict-free LDS.64 (banks 20g+tig)
#define A_STW (128 * A_LD)             // 5120 words
#define B_STW (4 * 128 * 8)            // 4096 words
#define STW   (A_STW + B_STW)          // 9216 words
#define STAGES 3
#define SMEM_BYTES (STAGES * STW * 4)  // 110,592 B

#define CP_ASYNC16(dst, src) \
    asm volatile("cp.async.cg.shared.global [%0], [%1], 16;\n" :: "r"(dst), "l"(src))
#define CP_COMMIT() asm volatile("cp.async.commit_group;\n")
#define CP_WAIT2()  asm volatile("cp.async.wait_group 2;\n")

__device__ __forceinline__ void mma8(float* c, const unsigned* a, const unsigned* b) {
    asm volatile(
        "mma.sync.aligned.m16n8k8.row.col.f32.tf32.tf32.f32 "
        "{%0,%1,%2,%3}, {%4,%5,%6,%7}, {%8,%9}, {%0,%1,%2,%3};\n"
        : "+f"(c[0]), "+f"(c[1]), "+f"(c[2]), "+f"(c[3])
        : "r"(a[0]), "r"(a[1]), "r"(a[2]), "r"(a[3]), "r"(b[0]), "r"(b[1]));
}

__global__ void __launch_bounds__(128, 2) gemm_k(float* __restrict__ out) {
    extern __shared__ unsigned sm[];
    const unsigned smem_base = (unsigned)__cvta_generic_to_shared(sm);

    const int b     = blockIdx.z;
    const int mBase = blockIdx.x * 128;     // s
    const int nBase = blockIdx.y * 128;     // o

    const int tid  = threadIdx.x;
    const int warp = tid >> 5;
    const int lane = tid & 31;
    const int wm   = (warp >> 1) * 64;      // warp s offset (0/64)
    const int wn   = (warp & 1) * 64;       // warp o offset (0/64)
    const int g    = lane >> 2;
    const int tig  = lane & 3;

    const float* gA = g_colT + ((size_t)b * S + mBase) * R;

    float acc[4][8][4];
#pragma unroll
    for (int i = 0; i < 4; i++)
#pragma unroll
        for (int j = 0; j < 8; j++)
#pragma unroll
            for (int k = 0; k < 4; k++) acc[i][j][k] = 0.0f;

    auto fill = [&](int st, int kt) {
        const int kb = kt * KTILE;
        const unsigned sa = smem_base + st * (STW * 4);
        const unsigned sb = sa + A_STW * 4;
#pragma unroll
        for (int i = 0; i < 8; i++) {        // A: 1024 x 16B granules
            const int gdx = i * 128 + tid;
            const int r = gdx >> 3, c4 = gdx & 7;
            CP_ASYNC16(sa + ((r * A_LD + c4 * 4) << 2),
                       gA + (size_t)r * R + kb + c4 * 4);
        }
        const float* gBk = g_wtp + ((size_t)(kb >> 3) * COUT + nBase) * 8;
#pragma unroll
        for (int i = 0; i < 8; i++) {        // B: 1024 x 16B granules
            const int gdx = i * 128 + tid;
            const int oct = gdx >> 8;
            const int rem = gdx & 255;
            const int ol  = rem >> 1;
            const int hf  = rem & 1;
            CP_ASYNC16(sb + (((oct * 128 + ol) * 8 + hf * 4) << 2),
                       gBk + ((size_t)oct * COUT + ol) * 8 + hf * 4);
        }
    };

    fill(0, 0); CP_COMMIT();
    fill(1, 1); CP_COMMIT();

    for (int kt = 0; kt < NKT; kt++) {
        __syncthreads();
        const int pf = kt + 2;
        if (pf < NKT) {
            int pst = kt + 2; pst -= (pst / STAGES) * STAGES;
            fill(pst, pf);
        }
        CP_COMMIT();
        CP_WAIT2();
        __syncthreads();

        int cs = kt - (kt / STAGES) * STAGES;
        const unsigned* A  = sm + cs * STW;
        const unsigned* Bm = A + A_STW;

#pragma unroll
        for (int ks = 0; ks < 4; ks++) {
            unsigned af[4][4], bf[8][2];
#pragma unroll
            for (int mt = 0; mt < 4; mt++) {
                const int base = (wm + mt * 16 + g) * A_LD + ks * 8 + tig * 2;
                uint2 a01 = *(const uint2*)(A + base);            // logical (kk, kk+4) @ row
                uint2 a23 = *(const uint2*)(A + base + 8 * A_LD); // @ row+8
                af[mt][0] = a01.x; af[mt][1] = a23.x;
                af[mt][2] = a01.y; af[mt][3] = a23.y;
            }
#pragma unroll
            for (int nt = 0; nt < 8; nt++) {
                const int nc = wn + nt * 8 + g;
                uint2 t = *(const uint2*)(Bm + ((ks * 128 + nc) << 3) + (tig << 1));
                bf[nt][0] = t.x;
                bf[nt][1] = t.y;
            }
#pragma unroll
            for (int mt = 0; mt < 4; mt++)
#pragma unroll
                for (int nt = 0; nt < 8; nt++)
                    mma8(acc[mt][nt], af[mt], bf[nt]);
        }
    }

    // ---- epilogue: transpose C[s][o] tile -> out[b][o][s] via smem ----
    __syncthreads();
    float* stg = (float*)sm;                  // [128 o][132]
#pragma unroll
    for (int mt = 0; mt < 4; mt++) {
#pragma unroll
        for (int nt = 0; nt < 8; nt++) {
            const int ol = wn + nt * 8 + 2 * tig;
            const int sl = wm + mt * 16 + g;
            stg[ol * 132 + sl]             = acc[mt][nt][0];
            stg[(ol + 1) * 132 + sl]       = acc[mt][nt][1];
            stg[ol * 132 + sl + 8]         = acc[mt][nt][2];
            stg[(ol + 1) * 132 + sl + 8]   = acc[mt][nt][3];
        }
    }
    __syncthreads();

    float* ob = out + ((size_t)b * COUT + nBase) * S + mBase;
#pragma unroll
    for (int i = 0; i < 32; i++) {
        const int e  = i * 128 + tid;
        const int o  = e >> 5;
        const int l4 = e & 31;
        *(float4*)(ob + (size_t)o * S + 4 * l4) = *(float4*)&stg[o * 132 + 4 * l4];
    }
}

// ---------------------------------------------------------------------------
// Single default stream — no stream/event objects (harness forbids the
// driver-side allocations they imply).
// ---------------------------------------------------------------------------
extern "C" void kernel_launch(void* const* d_in, const int* in_sizes, int n_in,
                              void* d_out, int out_size) {
    const float* x   = (const float*)d_in[0];
    const float* off = (const float*)d_in[1];
    const float* wt  = (const float*)d_in[2];
    float* out       = (float*)d_out;

    cvtw_k<<<(COUT * R) / 512, 512>>>(wt);
    trans_k<<<dim3(S / 32, CIN / 32, BATCH), dim3(32, 8)>>>(x);
    im2colT_k<<<dim3(S / 8, BATCH), 256>>>(off);

    cudaFuncSetAttribute(gemm_k, cudaFuncAttributeMaxDynamicSharedMemorySize,
                         SMEM_BYTES);
    gemm_k<<<dim3(S / 128, COUT / 128, BATCH), 128, SMEM_BYTES>>>(out);
}